// round 3
// baseline (speedup 1.0000x reference)
#include <cuda_runtime.h>
#include <cstdint>

#define BB 1024
#define TT 512
#define II 64
#define HH 32

typedef unsigned long long ull;

// Scratch: x_proj with b_ih+b_hh folded in, layout [t][b][k]  (64 MB, fits L2 for reads)
__device__ float g_xp[(size_t)TT * BB * HH];

// ---------- packed f32x2 helpers ----------
__device__ __forceinline__ ull pk(float lo, float hi) {
    ull r; asm("mov.b64 %0, {%1,%2};" : "=l"(r) : "f"(lo), "f"(hi)); return r;
}
__device__ __forceinline__ float2 upk(ull v) {
    float2 f; asm("mov.b64 {%0,%1}, %2;" : "=f"(f.x), "=f"(f.y) : "l"(v)); return f;
}
__device__ __forceinline__ ull fma2(ull a, ull b, ull c) {
    ull d; asm("fma.rn.f32x2 %0, %1, %2, %3;" : "=l"(d) : "l"(a), "l"(b), "l"(c)); return d;
}
__device__ __forceinline__ ull mul2(ull a, ull b) {
    ull d; asm("mul.rn.f32x2 %0, %1, %2;" : "=l"(d) : "l"(a), "l"(b)); return d;
}
__device__ __forceinline__ ull add2(ull a, ull b) {
    ull d; asm("add.rn.f32x2 %0, %1, %2;" : "=l"(d) : "l"(a), "l"(b)); return d;
}

// Fast exact tanh: 1 - 2/(exp(2x)+1). Saturates correctly at +/-1, no NaN.
__device__ __forceinline__ float ftanh(float x) {
    float e = __expf(2.0f * x);
    return 1.0f - __fdividef(2.0f, e + 1.0f);
}

// =====================================================================
// Kernel 1: x_proj.  xp[t][b][k] = sum_i x[b][t][i]*W_ih[k][i] + b_ih[k] + b_hh[k]
// Tile: 64 consecutive (b,t) rows per block (64 | T so a tile never crosses b).
// x rows packed pairwise into f32x2 in smem; all MACs are fma.rn.f32x2.
// =====================================================================
__global__ __launch_bounds__(128) void xproj_kernel(
    const float* __restrict__ x, const float* __restrict__ W_ih,
    const float* __restrict__ b_ih, const float* __restrict__ b_hh)
{
    __shared__ ulonglong2 sm_x[64 * 16];   // xs2[i][rp] : {x[2rp][i], x[2rp+1][i]}
    __shared__ ulonglong2 sm_w[64 * 16];   // wT [i][k]  : {w, w},  w = W_ih[k][i]
    ull* xs2 = (ull*)sm_x;
    ull* wT  = (ull*)sm_w;
    const int tid = threadIdx.x;

    // Build duplicated W table (2048 entries, once per block)
    #pragma unroll
    for (int e = 0; e < 16; e++) {
        int idx = tid * 16 + e;           // idx = i*32 + k
        int i = idx >> 5, k = idx & 31;
        float w = W_ih[k * II + i];
        wT[idx] = pk(w, w);
    }

    // Stage x tile: lane owns row pair (2rp, 2rp+1), i-range [half*16, +16)
    const float* xt = x + (size_t)blockIdx.x * 64 * II;
    const int rp = tid & 31, half = tid >> 5, i0 = half * 16;
    float4 av4[4], bv4[4];
    const float4* ra = (const float4*)(xt + (2 * rp) * II + i0);
    const float4* rb = (const float4*)(xt + (2 * rp + 1) * II + i0);
    #pragma unroll
    for (int u = 0; u < 4; u++) { av4[u] = ra[u]; bv4[u] = rb[u]; }
    const float* av = (const float*)av4;
    const float* bv = (const float*)bv4;
    #pragma unroll
    for (int u = 0; u < 16; u++) xs2[(i0 + u) * 32 + rp] = pk(av[u], bv[u]);
    __syncthreads();

    // Compute: thread owns 4 row-pairs (rpg) x 2 hidden units (k0,k0+1)
    const int rpg = tid >> 4, kg = tid & 15, k0 = kg * 2;
    float bias0 = b_ih[k0]     + b_hh[k0];
    float bias1 = b_ih[k0 + 1] + b_hh[k0 + 1];
    ull A00 = pk(bias0, bias0), A10 = A00, A20 = A00, A30 = A00;
    ull A01 = pk(bias1, bias1), A11 = A01, A21 = A01, A31 = A01;

    #pragma unroll 8
    for (int i = 0; i < II; i++) {
        const ull* xr = xs2 + i * 32 + rpg * 4;
        ulonglong2 xa = *(const ulonglong2*)xr;
        ulonglong2 xb = *(const ulonglong2*)(xr + 2);
        ulonglong2 wv = *(const ulonglong2*)(wT + i * 32 + k0);
        A00 = fma2(wv.x, xa.x, A00); A10 = fma2(wv.x, xa.y, A10);
        A20 = fma2(wv.x, xb.x, A20); A30 = fma2(wv.x, xb.y, A30);
        A01 = fma2(wv.y, xa.x, A01); A11 = fma2(wv.y, xa.y, A11);
        A21 = fma2(wv.y, xb.x, A21); A31 = fma2(wv.y, xb.y, A31);
    }

    // Write xp[t][b][k]; component .x -> row rf, .y -> row rf+1 (t+1, same b)
    const ull Ar[4][2] = {{A00,A01},{A10,A11},{A20,A21},{A30,A31}};
    const int rfbase = blockIdx.x * 64 + rpg * 8;
    #pragma unroll
    for (int r = 0; r < 4; r++) {
        int rf = rfbase + 2 * r;
        int b = rf >> 9, t = rf & 511;
        #pragma unroll
        for (int kk = 0; kk < 2; kk++) {
            float2 f = upk(Ar[r][kk]);
            g_xp[((size_t)t       * BB + b) * HH + k0 + kk] = f.x;
            g_xp[((size_t)(t + 1) * BB + b) * HH + k0 + kk] = f.y;
        }
    }
}

// =====================================================================
// Kernel 2: recurrence + fused output head.
// One warp per 4 batch elements. lane = hidden unit k. h kept in smem as
// f32x2 pairs (ping-pong buffers, 1 syncwarp/step). W_hh row pre-packed in regs.
// out[b][t] = Wout . h_t reduced via butterfly shfl (off the recurrence path).
// =====================================================================
__global__ __launch_bounds__(32) void rnn_kernel(
    const float* __restrict__ h0, const float* __restrict__ W_hh,
    const float* __restrict__ W_out, const float* __restrict__ b_out,
    float* __restrict__ out, int write_hlast)
{
    __shared__ ulonglong2 hs[2][HH];
    const int k = threadIdx.x;
    const int b0 = blockIdx.x * 4;

    ull wp[HH];
    #pragma unroll
    for (int j = 0; j < HH; j++) { float w = W_hh[k * HH + j]; wp[j] = pk(w, w); }
    const float wo = W_out[k];
    const ull wop = pk(wo, wo);
    const float bo = b_out[0];

    // init h from h0
    {
        float h00 = h0[(b0 + 0) * HH + k], h01 = h0[(b0 + 1) * HH + k];
        float h02 = h0[(b0 + 2) * HH + k], h03 = h0[(b0 + 3) * HH + k];
        hs[0][k] = make_ulonglong2(pk(h00, h01), pk(h02, h03));
    }
    __syncwarp();

    // preload xp for t=0
    const float* xp0 = g_xp + (size_t)b0 * HH + k;
    float c0 = xp0[0], c1 = xp0[HH], c2 = xp0[2 * HH], c3 = xp0[3 * HH];

    int p = 0;
    float ha0 = 0.f, ha1 = 0.f, ha2 = 0.f, ha3 = 0.f;

    #pragma unroll 1
    for (int t = 0; t < TT; t++) {
        ull accA = pk(c0, c1);
        ull accB = pk(c2, c3);

        // prefetch xp for t+1 (L2-resident; overlaps the FMA chain below)
        int tn = (t + 1 < TT) ? (t + 1) : t;
        const float* xq = g_xp + ((size_t)tn * BB + b0) * HH + k;
        float n0 = __ldg(xq), n1 = __ldg(xq + HH), n2 = __ldg(xq + 2 * HH), n3 = __ldg(xq + 3 * HH);

        const ulonglong2* hb = hs[p];
        #pragma unroll
        for (int j = 0; j < HH; j++) {
            ulonglong2 hv = hb[j];               // broadcast LDS.128
            accA = fma2(wp[j], hv.x, accA);
            accB = fma2(wp[j], hv.y, accB);
        }

        float2 fa = upk(accA), fb = upk(accB);
        ha0 = ftanh(fa.x); ha1 = ftanh(fa.y);
        ha2 = ftanh(fb.x); ha3 = ftanh(fb.y);
        ull hnA = pk(ha0, ha1), hnB = pk(ha2, ha3);
        hs[p ^ 1][k] = make_ulonglong2(hnA, hnB);
        __syncwarp();

        // output head (independent of recurrence critical path)
        ull ra = mul2(wop, hnA), rb = mul2(wop, hnB);
        #pragma unroll
        for (int m = 16; m; m >>= 1) {
            ra = add2(ra, __shfl_xor_sync(0xffffffffu, ra, m));
            rb = add2(rb, __shfl_xor_sync(0xffffffffu, rb, m));
        }
        if (k < 4) {
            float2 f = upk(k < 2 ? ra : rb);
            float v = ((k & 1) ? f.y : f.x) + bo;
            out[(size_t)(b0 + k) * TT + t] = v;
        }

        c0 = n0; c1 = n1; c2 = n2; c3 = n3;
        p ^= 1;
    }

    if (write_hlast) {
        float* hl = out + (size_t)BB * TT;
        hl[(b0 + 0) * HH + k] = ha0;
        hl[(b0 + 1) * HH + k] = ha1;
        hl[(b0 + 2) * HH + k] = ha2;
        hl[(b0 + 3) * HH + k] = ha3;
    }
}

extern "C" void kernel_launch(void* const* d_in, const int* in_sizes, int n_in,
                              void* d_out, int out_size) {
    const float* x     = (const float*)d_in[0];
    const float* h0    = (const float*)d_in[1];
    const float* W_ih  = (const float*)d_in[2];
    const float* b_ih  = (const float*)d_in[3];
    const float* W_hh  = (const float*)d_in[4];
    const float* b_hh  = (const float*)d_in[5];
    const float* W_out = (const float*)d_in[6];
    const float* b_out = (const float*)d_in[7];
    float* out = (float*)d_out;

    xproj_kernel<<<(BB * TT) / 64, 128>>>(x, W_ih, b_ih, b_hh);

    int wh = (out_size >= BB * TT + BB * HH) ? 1 : 0;
    rnn_kernel<<<BB / 4, 32>>>(h0, W_hh, W_out, b_out, out, wh);
}

// round 5
// speedup vs baseline: 2.4516x; 2.4516x over previous
#include <cuda_runtime.h>
#include <cstdint>

#define BB 1024
#define TT 512
#define II 64
#define HH 32

typedef unsigned long long ull;

// Scratch: x_proj with b_ih+b_hh folded in, layout [b][t][k]  (64 MB)
__device__ float g_xp[(size_t)BB * TT * HH];

// ---------- packed f32x2 helpers ----------
__device__ __forceinline__ ull pk(float lo, float hi) {
    ull r; asm("mov.b64 %0, {%1,%2};" : "=l"(r) : "f"(lo), "f"(hi)); return r;
}
__device__ __forceinline__ float2 upk(ull v) {
    float2 f; asm("mov.b64 {%0,%1}, %2;" : "=f"(f.x), "=f"(f.y) : "l"(v)); return f;
}
__device__ __forceinline__ ull fma2(ull a, ull b, ull c) {
    ull d; asm("fma.rn.f32x2 %0, %1, %2, %3;" : "=l"(d) : "l"(a), "l"(b), "l"(c)); return d;
}
__device__ __forceinline__ ull mul2(ull a, ull b) {
    ull d; asm("mul.rn.f32x2 %0, %1, %2;" : "=l"(d) : "l"(a), "l"(b)); return d;
}
__device__ __forceinline__ ull add2(ull a, ull b) {
    ull d; asm("add.rn.f32x2 %0, %1, %2;" : "=l"(d) : "l"(a), "l"(b)); return d;
}

// Fast exact tanh: 1 - 2/(exp(2x)+1). Saturates correctly at +/-1, no NaN.
__device__ __forceinline__ float ftanh(float x) {
    float e = __expf(2.0f * x);
    return 1.0f - __fdividef(2.0f, e + 1.0f);
}

// =====================================================================
// Kernel 1: x_proj.  xp[b][t][k] = sum_i x[b][t][i]*W_ih[k][i] + b_ih[k] + b_hh[k]
// 128 rows (b,t flattened) per block; 128 threads.
// Register tile per thread: 8 row-pairs x 2 hidden units -> 16 fma2 / 5 LDS.128 per i.
// =====================================================================
__global__ __launch_bounds__(128) void xproj_kernel(
    const float* __restrict__ x, const float* __restrict__ W_ih,
    const float* __restrict__ b_ih, const float* __restrict__ b_hh)
{
    __shared__ ull sm[64 * 64 + 64 * 32];     // 48 KB exactly
    ull* xs2 = sm;                             // [i][rp] : {x[2rp][i], x[2rp+1][i]}, rp 0..63
    ull* wT  = sm + 64 * 64;                   // [i][k]  : {w, w}
    const int tid = threadIdx.x;

    // Build duplicated W table (2048 entries)
    #pragma unroll
    for (int e = 0; e < 16; e++) {
        int idx = tid * 16 + e;                // idx = i*32 + k
        int i = idx >> 5, k = idx & 31;
        float w = W_ih[k * II + i];
        wT[idx] = pk(w, w);
    }

    // Stage x tile: thread owns row-pair (tid>>1), i-half (tid&1)
    const float* xt = x + (size_t)blockIdx.x * 128 * II;
    const int rp = tid >> 1, half = tid & 1, i0 = half * 32;
    {
        const float4* ra = (const float4*)(xt + (2 * rp) * II + i0);
        const float4* rb = (const float4*)(xt + (2 * rp + 1) * II + i0);
        float4 av4[8], bv4[8];
        #pragma unroll
        for (int u = 0; u < 8; u++) { av4[u] = ra[u]; bv4[u] = rb[u]; }
        const float* av = (const float*)av4;
        const float* bv = (const float*)bv4;
        #pragma unroll
        for (int u = 0; u < 32; u++) xs2[(i0 + u) * 64 + rp] = pk(av[u], bv[u]);
    }
    __syncthreads();

    // Compute: thread owns row-pairs [rpg*8, rpg*8+8) x hidden units (k0, k0+1)
    const int kg = tid & 15, k0 = kg * 2, rpg = tid >> 4;
    const float bias0 = b_ih[k0]     + b_hh[k0];
    const float bias1 = b_ih[k0 + 1] + b_hh[k0 + 1];
    ull acc[8][2];
    #pragma unroll
    for (int u = 0; u < 8; u++) { acc[u][0] = pk(bias0, bias0); acc[u][1] = pk(bias1, bias1); }

    #pragma unroll 4
    for (int i = 0; i < II; i++) {
        ulonglong2 w2 = *(const ulonglong2*)(wT + i * 32 + k0);
        const ulonglong2* xr = (const ulonglong2*)(xs2 + i * 64 + rpg * 8);
        #pragma unroll
        for (int u = 0; u < 4; u++) {
            ulonglong2 xv = xr[u];
            acc[2*u  ][0] = fma2(w2.x, xv.x, acc[2*u  ][0]);
            acc[2*u  ][1] = fma2(w2.y, xv.x, acc[2*u  ][1]);
            acc[2*u+1][0] = fma2(w2.x, xv.y, acc[2*u+1][0]);
            acc[2*u+1][1] = fma2(w2.y, xv.y, acc[2*u+1][1]);
        }
    }

    // Writeout: g_xp row-major [row][k]; STG.64 of {k0, k0+1}
    const size_t rowbase = (size_t)blockIdx.x * 128;
    #pragma unroll
    for (int u = 0; u < 8; u++) {
        int rp2 = rpg * 8 + u;
        float2 f0 = upk(acc[u][0]);    // k0   : rows (2rp2, 2rp2+1)
        float2 f1 = upk(acc[u][1]);    // k0+1
        float2* o0 = (float2*)(g_xp + (rowbase + 2 * rp2)     * HH + k0);
        float2* o1 = (float2*)(g_xp + (rowbase + 2 * rp2 + 1) * HH + k0);
        *o0 = make_float2(f0.x, f1.x);
        *o1 = make_float2(f0.y, f1.y);
    }
}

// =====================================================================
// Kernel 2: recurrence, warp-specialized.
// Block = 64 threads (warp0 = producer recurrence, warp1 = consumer),
// 2 batch elements per block, 512 blocks.
// Producer: lane k = hidden unit; h kept in smem f32x2 ({b0,b1}); per step:
//   1 LDS.64 (xp from smem chunk) + 16 LDS.128 (h) + 32 fma2 (4 partial chains)
//   + tanh + 1 STS.64 (h) + 1 STS.64 (pbuf product) + syncwarp.
// Consumer: per 32-step chunk, prefetches next xp chunk (GMEM->smem) and
//   reduces pbuf -> out (lane = timestep, conflict-free padded layout).
// One __syncthreads per chunk boundary; double-buffered xbuf/pbuf.
// =====================================================================
__global__ __launch_bounds__(64) void rnn_kernel(
    const float* __restrict__ h0, const float* __restrict__ W_hh,
    const float* __restrict__ W_out, const float* __restrict__ b_out,
    float* __restrict__ out, int write_hlast)
{
    __shared__ ull xb[2][32 * 32];     // [par][tc*32 + k] = {xp[b0][t][k], xp[b1][t][k]}
    __shared__ ull pbuf[2][32 * 33];   // [par][k*33 + tc] = wo_k * h2   (padded rows)
    __shared__ ull hbuf[2][HH];        // ping-pong h state
    const int b0 = blockIdx.x * 2;
    const int lane = threadIdx.x & 31;
    const ull z = pk(0.0f, 0.0f);
    const int NC = TT / 32;            // 16 chunks

    if (threadIdx.x < 32) {
        // ---------------- producer warp ----------------
        const int k = lane;
        ull wp2[HH];
        #pragma unroll
        for (int j = 0; j < HH; j++) { float w = W_hh[k * HH + j]; wp2[j] = pk(w, w); }
        const float wo = W_out[k];
        const ull wop = pk(wo, wo);

        float hA = h0[b0 * HH + k];
        float hB = h0[(b0 + 1) * HH + k];
        hbuf[0][k] = pk(hA, hB);
        int p = 0;

        for (int c = 0; c < NC; c++) {
            __syncthreads();                       // xbuf[c&1] ready, pbuf[c&1] free
            const ull* xq = xb[c & 1];
            ull* pq = pbuf[c & 1];
            #pragma unroll 1
            for (int tc = 0; tc < 32; tc++) {
                ull a0 = xq[tc * 32 + k], a1 = z, a2 = z, a3 = z;
                const ulonglong2* hb2 = (const ulonglong2*)hbuf[p];
                #pragma unroll
                for (int m = 0; m < 16; m += 2) {
                    ulonglong2 hv = hb2[m];
                    a0 = fma2(wp2[2*m    ], hv.x, a0);
                    a1 = fma2(wp2[2*m + 1], hv.y, a1);
                    ulonglong2 hw = hb2[m + 1];
                    a2 = fma2(wp2[2*m + 2], hw.x, a2);
                    a3 = fma2(wp2[2*m + 3], hw.y, a3);
                }
                ull s = add2(add2(a0, a2), add2(a1, a3));
                float2 f = upk(s);
                hA = ftanh(f.x); hB = ftanh(f.y);
                ull h2 = pk(hA, hB);
                hbuf[p ^ 1][k] = h2;
                __syncwarp();
                pq[k * 33 + tc] = mul2(wop, h2);
                p ^= 1;
            }
        }
        __syncthreads();                           // final: pbuf[15&1] visible to consumer
        if (write_hlast) {
            float* hl = out + (size_t)BB * TT;
            hl[b0 * HH + k] = hA;
            hl[(b0 + 1) * HH + k] = hB;
        }
    } else {
        // ---------------- consumer warp ----------------
        const int l = lane;
        const float bo = b_out[0];
        const float4* src0 = (const float4*)(g_xp + (size_t)b0 * TT * HH);
        const float4* src1 = src0 + (TT * HH) / 4;

        // chunk loader: 8 KB -> xb[par], packed as f32x2 pairs {b0,b1}
        auto loadx = [&](int c) {
            const float4* s0 = src0 + (size_t)c * 32 * HH / 4;
            const float4* s1 = src1 + (size_t)c * 32 * HH / 4;
            ulonglong2* dst = (ulonglong2*)xb[c & 1];
            #pragma unroll
            for (int u = 0; u < 8; u++) {
                float4 a = s0[u * 32 + l];
                float4 b = s1[u * 32 + l];
                int idx = u * 32 + l;              // float4 index, 0..255
                int tc = idx >> 3, kq = idx & 7;   // k0 = kq*4
                dst[tc * 16 + kq * 2    ] = make_ulonglong2(pk(a.x, b.x), pk(a.y, b.y));
                dst[tc * 16 + kq * 2 + 1] = make_ulonglong2(pk(a.z, b.z), pk(a.w, b.w));
            }
        };
        // chunk reducer: out[b][t] = sum_k pbuf + b_out
        auto reduce = [&](int c) {
            const ull* pq = pbuf[c & 1];
            ull a0 = z, a1 = z, a2 = z, a3 = z;
            #pragma unroll
            for (int kk = 0; kk < 32; kk += 4) {
                a0 = add2(a0, pq[(kk    ) * 33 + l]);
                a1 = add2(a1, pq[(kk + 1) * 33 + l]);
                a2 = add2(a2, pq[(kk + 2) * 33 + l]);
                a3 = add2(a3, pq[(kk + 3) * 33 + l]);
            }
            float2 f = upk(add2(add2(a0, a1), add2(a2, a3)));
            out[(size_t)b0 * TT + c * 32 + l]       = f.x + bo;
            out[(size_t)(b0 + 1) * TT + c * 32 + l] = f.y + bo;
        };

        loadx(0);
        for (int c = 0; c < NC; c++) {
            __syncthreads();                       // publish xbuf[c&1]; producer pbuf[(c-1)&1] ready
            if (c + 1 < NC) loadx(c + 1);
            if (c > 0) reduce(c - 1);
        }
        __syncthreads();
        reduce(NC - 1);
    }
}

extern "C" void kernel_launch(void* const* d_in, const int* in_sizes, int n_in,
                              void* d_out, int out_size) {
    const float* x     = (const float*)d_in[0];
    const float* h0    = (const float*)d_in[1];
    const float* W_ih  = (const float*)d_in[2];
    const float* b_ih  = (const float*)d_in[3];
    const float* W_hh  = (const float*)d_in[4];
    const float* b_hh  = (const float*)d_in[5];
    const float* W_out = (const float*)d_in[6];
    const float* b_out = (const float*)d_in[7];
    float* out = (float*)d_out;

    xproj_kernel<<<(BB * TT) / 128, 128>>>(x, W_ih, b_ih, b_hh);

    int wh = (out_size >= BB * TT + BB * HH) ? 1 : 0;
    rnn_kernel<<<BB / 2, 64>>>(h0, W_hh, W_out, b_out, out, wh);
}

// round 6
// speedup vs baseline: 2.7652x; 1.1279x over previous
#include <cuda_runtime.h>
#include <cstdint>

#define BB 1024
#define TT 512
#define II 64
#define HH 32

typedef unsigned long long ull;

// Scratch: x_proj with b_ih+b_hh folded in, layout [b][t][k]  (64 MB)
__device__ float g_xp[(size_t)BB * TT * HH];

// ---------- packed f32x2 helpers ----------
__device__ __forceinline__ ull pk(float lo, float hi) {
    ull r; asm("mov.b64 %0, {%1,%2};" : "=l"(r) : "f"(lo), "f"(hi)); return r;
}
__device__ __forceinline__ float2 upk(ull v) {
    float2 f; asm("mov.b64 {%0,%1}, %2;" : "=f"(f.x), "=f"(f.y) : "l"(v)); return f;
}
__device__ __forceinline__ ull fma2(ull a, ull b, ull c) {
    ull d; asm("fma.rn.f32x2 %0, %1, %2, %3;" : "=l"(d) : "l"(a), "l"(b), "l"(c)); return d;
}
__device__ __forceinline__ ull mul2(ull a, ull b) {
    ull d; asm("mul.rn.f32x2 %0, %1, %2;" : "=l"(d) : "l"(a), "l"(b)); return d;
}
__device__ __forceinline__ ull add2(ull a, ull b) {
    ull d; asm("add.rn.f32x2 %0, %1, %2;" : "=l"(d) : "l"(a), "l"(b)); return d;
}

// Fast exact tanh: 1 - 2/(exp(2x)+1). Saturates correctly at +/-1, no NaN.
__device__ __forceinline__ float ftanh(float x) {
    float e = __expf(2.0f * x);
    return 1.0f - __fdividef(2.0f, e + 1.0f);
}

// =====================================================================
// Kernel 1: x_proj (register-direct, no x staging).
// xp[b][t][k] = sum_i x[b][t][i]*W_ih[k][i] + b_ih[k] + b_hh[k]
// Block = 128 threads, each thread owns 2 consecutive rows (b,t flattened).
// W table in smem as {W[2kp][i], W[2kp+1][i]} pairs -> warp-uniform
// broadcast LDS.128 (conflict-free). Accumulators packed {k,k+1} so the
// writeout is contiguous STG.128.
// =====================================================================
__global__ __launch_bounds__(128) void xproj_kernel(
    const float* __restrict__ x, const float* __restrict__ W_ih,
    const float* __restrict__ b_ih, const float* __restrict__ b_hh)
{
    __shared__ ull wT[II * 16];      // [i][kp] = {W[2kp][i], W[2kp+1][i]}   8 KB
    __shared__ ull bias2[16];
    const int tid = threadIdx.x;

    #pragma unroll
    for (int r = 0; r < 8; r++) {
        int e = tid + r * 128;                 // e = i*16 + kp
        int i = e >> 4, kp = e & 15;
        wT[e] = pk(W_ih[(2 * kp) * II + i], W_ih[(2 * kp + 1) * II + i]);
    }
    if (tid < 16)
        bias2[tid] = pk(b_ih[2 * tid] + b_hh[2 * tid],
                        b_ih[2 * tid + 1] + b_hh[2 * tid + 1]);
    __syncthreads();

    const size_t row0 = (size_t)blockIdx.x * 256 + tid * 2;
    const float4* xr0 = (const float4*)(x + row0 * II);
    const float4* xr1 = (const float4*)(x + (row0 + 1) * II);

    ull acc0[16], acc1[16];
    #pragma unroll
    for (int kp = 0; kp < 16; kp++) { ull b = bias2[kp]; acc0[kp] = b; acc1[kp] = b; }

    #pragma unroll
    for (int ic = 0; ic < 4; ic++) {
        float4 xa[4], xb4[4];
        #pragma unroll
        for (int u = 0; u < 4; u++) { xa[u] = xr0[ic * 4 + u]; xb4[u] = xr1[ic * 4 + u]; }
        const float* fa = (const float*)xa;
        const float* fb = (const float*)xb4;
        #pragma unroll
        for (int ii = 0; ii < 16; ii++) {
            const int i = ic * 16 + ii;
            const ull xd0 = pk(fa[ii], fa[ii]);
            const ull xd1 = pk(fb[ii], fb[ii]);
            const ulonglong2* wrow = (const ulonglong2*)(wT + i * 16);
            #pragma unroll
            for (int kq = 0; kq < 8; kq++) {
                ulonglong2 w2 = wrow[kq];      // broadcast LDS.128
                acc0[2 * kq]     = fma2(w2.x, xd0, acc0[2 * kq]);
                acc0[2 * kq + 1] = fma2(w2.y, xd0, acc0[2 * kq + 1]);
                acc1[2 * kq]     = fma2(w2.x, xd1, acc1[2 * kq]);
                acc1[2 * kq + 1] = fma2(w2.y, xd1, acc1[2 * kq + 1]);
            }
        }
    }

    ulonglong2* o0 = (ulonglong2*)(g_xp + row0 * HH);
    ulonglong2* o1 = (ulonglong2*)(g_xp + (row0 + 1) * HH);
    #pragma unroll
    for (int kq = 0; kq < 8; kq++) {
        o0[kq] = make_ulonglong2(acc0[2 * kq], acc0[2 * kq + 1]);
        o1[kq] = make_ulonglong2(acc1[2 * kq], acc1[2 * kq + 1]);
    }
}

// =====================================================================
// Kernel 2: recurrence, warp-specialized (producer/consumer), 2 batches/block.
// Producer per step: xq in reg (prefetched 1 step ahead), 16 broadcast
// LDS.128 of h, 32 fma2 into 8 partial chains (depth 4), 3-level add2 tree,
// exact tanh, STS h, syncwarp; pbuf product after the sync (off-chain).
// Consumer per 32-step chunk: GMEM->smem xp prefetch + pbuf reduction.
// =====================================================================
__global__ __launch_bounds__(64) void rnn_kernel(
    const float* __restrict__ h0, const float* __restrict__ W_hh,
    const float* __restrict__ W_out, const float* __restrict__ b_out,
    float* __restrict__ out, int write_hlast)
{
    __shared__ ull xb[2][32 * 32];     // [par][tc*32 + k] = {xp[b0][t][k], xp[b1][t][k]}
    __shared__ ull pbuf[2][32 * 33];   // [par][k*33 + tc] = wo_k * h2   (padded rows)
    __shared__ ull hbuf[2][HH];        // ping-pong h state
    const int b0 = blockIdx.x * 2;
    const int lane = threadIdx.x & 31;
    const ull z = pk(0.0f, 0.0f);
    const int NC = TT / 32;            // 16 chunks

    if (threadIdx.x < 32) {
        // ---------------- producer warp ----------------
        const int k = lane;
        ull wp2[HH];
        #pragma unroll
        for (int j = 0; j < HH; j++) { float w = W_hh[k * HH + j]; wp2[j] = pk(w, w); }
        const float wo = W_out[k];
        const ull wop = pk(wo, wo);

        float hA = h0[b0 * HH + k];
        float hB = h0[(b0 + 1) * HH + k];
        hbuf[0][k] = pk(hA, hB);
        int p = 0;

        for (int c = 0; c < NC; c++) {
            __syncthreads();                       // xbuf[c&1] ready, pbuf[c&1] free
            const ull* xq = xb[c & 1];
            ull* pq = pbuf[c & 1];
            ull xcur = xq[k];
            #pragma unroll 2
            for (int tc = 0; tc < 32; tc++) {
                // prefetch next step's xp (independent of h chain)
                ull xnext = (tc + 1 < 32) ? xq[(tc + 1) * 32 + k] : xcur;

                ull a0 = xcur, a1 = z, a2 = z, a3 = z;
                ull a4 = z, a5 = z, a6 = z, a7 = z;
                const ulonglong2* hb2 = (const ulonglong2*)hbuf[p];
                #pragma unroll
                for (int m = 0; m < 16; m += 4) {
                    ulonglong2 h0v = hb2[m];
                    a0 = fma2(wp2[2 * m    ], h0v.x, a0);
                    a1 = fma2(wp2[2 * m + 1], h0v.y, a1);
                    ulonglong2 h1v = hb2[m + 1];
                    a2 = fma2(wp2[2 * m + 2], h1v.x, a2);
                    a3 = fma2(wp2[2 * m + 3], h1v.y, a3);
                    ulonglong2 h2v = hb2[m + 2];
                    a4 = fma2(wp2[2 * m + 4], h2v.x, a4);
                    a5 = fma2(wp2[2 * m + 5], h2v.y, a5);
                    ulonglong2 h3v = hb2[m + 3];
                    a6 = fma2(wp2[2 * m + 6], h3v.x, a6);
                    a7 = fma2(wp2[2 * m + 7], h3v.y, a7);
                }
                ull t0 = add2(a0, a4), t1 = add2(a1, a5);
                ull t2 = add2(a2, a6), t3 = add2(a3, a7);
                ull s = add2(add2(t0, t2), add2(t1, t3));
                float2 f = upk(s);
                hA = ftanh(f.x); hB = ftanh(f.y);
                ull h2 = pk(hA, hB);
                hbuf[p ^ 1][k] = h2;
                __syncwarp();
                pq[k * 33 + tc] = mul2(wop, h2);   // off the recurrence chain
                xcur = xnext;
                p ^= 1;
            }
        }
        __syncthreads();                           // final pbuf visible to consumer
        if (write_hlast) {
            float* hl = out + (size_t)BB * TT;
            hl[b0 * HH + k] = hA;
            hl[(b0 + 1) * HH + k] = hB;
        }
    } else {
        // ---------------- consumer warp ----------------
        const int l = lane;
        const float bo = b_out[0];
        const float4* src0 = (const float4*)(g_xp + (size_t)b0 * TT * HH);
        const float4* src1 = src0 + (TT * HH) / 4;

        // chunk loader: 8 KB -> xb[par], packed as f32x2 pairs {b0,b1}
        auto loadx = [&](int c) {
            const float4* s0 = src0 + (size_t)c * 32 * HH / 4;
            const float4* s1 = src1 + (size_t)c * 32 * HH / 4;
            ulonglong2* dst = (ulonglong2*)xb[c & 1];
            #pragma unroll
            for (int u = 0; u < 8; u++) {
                float4 a = s0[u * 32 + l];
                float4 b = s1[u * 32 + l];
                int idx = u * 32 + l;              // float4 index, 0..255
                int tc = idx >> 3, kq = idx & 7;   // k0 = kq*4
                dst[tc * 16 + kq * 2    ] = make_ulonglong2(pk(a.x, b.x), pk(a.y, b.y));
                dst[tc * 16 + kq * 2 + 1] = make_ulonglong2(pk(a.z, b.z), pk(a.w, b.w));
            }
        };
        // chunk reducer: out[b][t] = sum_k pbuf + b_out
        auto reduce = [&](int c) {
            const ull* pq = pbuf[c & 1];
            ull a0 = z, a1 = z, a2 = z, a3 = z;
            #pragma unroll
            for (int kk = 0; kk < 32; kk += 4) {
                a0 = add2(a0, pq[(kk    ) * 33 + l]);
                a1 = add2(a1, pq[(kk + 1) * 33 + l]);
                a2 = add2(a2, pq[(kk + 2) * 33 + l]);
                a3 = add2(a3, pq[(kk + 3) * 33 + l]);
            }
            float2 f = upk(add2(add2(a0, a1), add2(a2, a3)));
            out[(size_t)b0 * TT + c * 32 + l]       = f.x + bo;
            out[(size_t)(b0 + 1) * TT + c * 32 + l] = f.y + bo;
        };

        loadx(0);
        for (int c = 0; c < NC; c++) {
            __syncthreads();                       // publish xbuf[c&1]
            if (c + 1 < NC) loadx(c + 1);
            if (c > 0) reduce(c - 1);
        }
        __syncthreads();
        reduce(NC - 1);
    }
}

extern "C" void kernel_launch(void* const* d_in, const int* in_sizes, int n_in,
                              void* d_out, int out_size) {
    const float* x     = (const float*)d_in[0];
    const float* h0    = (const float*)d_in[1];
    const float* W_ih  = (const float*)d_in[2];
    const float* b_ih  = (const float*)d_in[3];
    const float* W_hh  = (const float*)d_in[4];
    const float* b_hh  = (const float*)d_in[5];
    const float* W_out = (const float*)d_in[6];
    const float* b_out = (const float*)d_in[7];
    float* out = (float*)d_out;

    xproj_kernel<<<(BB * TT) / 256, 128>>>(x, W_ih, b_ih, b_hh);

    int wh = (out_size >= BB * TT + BB * HH) ? 1 : 0;
    rnn_kernel<<<BB / 2, 64>>>(h0, W_hh, W_out, b_out, out, wh);
}

// round 7
// speedup vs baseline: 3.0268x; 1.0946x over previous
#include <cuda_runtime.h>
#include <cstdint>

#define BB 1024
#define TT 512
#define II 64
#define HH 32

typedef unsigned long long ull;

// Scratch: x_proj with b_ih+b_hh folded in, layout [b][t][k]  (64 MB)
__device__ float g_xp[(size_t)BB * TT * HH];

// ---------- packed f32x2 helpers ----------
__device__ __forceinline__ ull pk(float lo, float hi) {
    ull r; asm("mov.b64 %0, {%1,%2};" : "=l"(r) : "f"(lo), "f"(hi)); return r;
}
__device__ __forceinline__ float2 upk(ull v) {
    float2 f; asm("mov.b64 {%0,%1}, %2;" : "=f"(f.x), "=f"(f.y) : "l"(v)); return f;
}
__device__ __forceinline__ ull fma2(ull a, ull b, ull c) {
    ull d; asm("fma.rn.f32x2 %0, %1, %2, %3;" : "=l"(d) : "l"(a), "l"(b), "l"(c)); return d;
}
__device__ __forceinline__ ull mul2(ull a, ull b) {
    ull d; asm("mul.rn.f32x2 %0, %1, %2;" : "=l"(d) : "l"(a), "l"(b)); return d;
}
__device__ __forceinline__ ull add2(ull a, ull b) {
    ull d; asm("add.rn.f32x2 %0, %1, %2;" : "=l"(d) : "l"(a), "l"(b)); return d;
}

// Fast exact tanh: 1 - 2/(exp(2x)+1). Saturates correctly at +/-1, no NaN.
__device__ __forceinline__ float ftanh(float x) {
    float e = __expf(2.0f * x);
    return 1.0f - __fdividef(2.0f, e + 1.0f);
}

__device__ __forceinline__ void pair_bar(int pairid) {
    asm volatile("bar.sync %0, 64;" :: "r"(pairid + 1) : "memory");
}

// =====================================================================
// Kernel 1: x_proj (register-direct, double-buffered x prefetch).
// xp[b][t][k] = sum_i x[b][t][i]*W_ih[k][i] + b_ih[k] + b_hh[k]
// =====================================================================
__global__ __launch_bounds__(128) void xproj_kernel(
    const float* __restrict__ x, const float* __restrict__ W_ih,
    const float* __restrict__ b_ih, const float* __restrict__ b_hh)
{
    __shared__ ull wT[II * 16];      // [i][kp] = {W[2kp][i], W[2kp+1][i]}   8 KB
    __shared__ ull bias2[16];
    const int tid = threadIdx.x;

    #pragma unroll
    for (int r = 0; r < 8; r++) {
        int e = tid + r * 128;                 // e = i*16 + kp
        int i = e >> 4, kp = e & 15;
        wT[e] = pk(W_ih[(2 * kp) * II + i], W_ih[(2 * kp + 1) * II + i]);
    }
    if (tid < 16)
        bias2[tid] = pk(b_ih[2 * tid] + b_hh[2 * tid],
                        b_ih[2 * tid + 1] + b_hh[2 * tid + 1]);
    __syncthreads();

    const size_t row0 = (size_t)blockIdx.x * 256 + tid * 2;
    const float4* xr0 = (const float4*)(x + row0 * II);
    const float4* xr1 = (const float4*)(x + (row0 + 1) * II);

    ull acc0[16], acc1[16];
    #pragma unroll
    for (int kp = 0; kp < 16; kp++) { ull b = bias2[kp]; acc0[kp] = b; acc1[kp] = b; }

    float4 bufA[2][4], bufB[2][4];
    #pragma unroll
    for (int u = 0; u < 4; u++) { bufA[0][u] = xr0[u]; bufB[0][u] = xr1[u]; }

    #pragma unroll
    for (int ic = 0; ic < 4; ic++) {
        const int cu = ic & 1;
        if (ic < 3) {
            #pragma unroll
            for (int u = 0; u < 4; u++) {
                bufA[cu ^ 1][u] = xr0[(ic + 1) * 4 + u];
                bufB[cu ^ 1][u] = xr1[(ic + 1) * 4 + u];
            }
        }
        const float* fa = (const float*)bufA[cu];
        const float* fb = (const float*)bufB[cu];
        #pragma unroll
        for (int ii = 0; ii < 16; ii++) {
            const int i = ic * 16 + ii;
            const ull xd0 = pk(fa[ii], fa[ii]);
            const ull xd1 = pk(fb[ii], fb[ii]);
            const ulonglong2* wrow = (const ulonglong2*)(wT + i * 16);
            #pragma unroll
            for (int kq = 0; kq < 8; kq++) {
                ulonglong2 w2 = wrow[kq];      // broadcast LDS.128
                acc0[2 * kq]     = fma2(w2.x, xd0, acc0[2 * kq]);
                acc0[2 * kq + 1] = fma2(w2.y, xd0, acc0[2 * kq + 1]);
                acc1[2 * kq]     = fma2(w2.x, xd1, acc1[2 * kq]);
                acc1[2 * kq + 1] = fma2(w2.y, xd1, acc1[2 * kq + 1]);
            }
        }
    }

    ulonglong2* o0 = (ulonglong2*)(g_xp + row0 * HH);
    ulonglong2* o1 = (ulonglong2*)(g_xp + (row0 + 1) * HH);
    #pragma unroll
    for (int kq = 0; kq < 8; kq++) {
        o0[kq] = make_ulonglong2(acc0[2 * kq], acc0[2 * kq + 1]);
        o1[kq] = make_ulonglong2(acc1[2 * kq], acc1[2 * kq + 1]);
    }
}

// =====================================================================
// Kernel 2: recurrence. 256-thread blocks = 4 independent producer/consumer
// pairs; producers are warps 0-3 (one per SMSP -> no scheduler contention),
// consumers are warps 4-7. Pair p handles batches (blockIdx*8 + 2p, +2p+1).
// Sync: per-pair named barrier (bar.sync p+1, 64), chunk = 8 steps.
// Producer per step: LDS.64 xq + 16 broadcast LDS.128 h + 32 fma2 (8 chains)
// + add tree + exact tanh + STS h + syncwarp; pbuf product off-chain.
// Consumer per chunk: GMEM->smem xp prefetch (next chunk) + pbuf reduction.
// =====================================================================
__global__ __launch_bounds__(256) void rnn_kernel(
    const float* __restrict__ h0, const float* __restrict__ W_hh,
    const float* __restrict__ W_out, const float* __restrict__ b_out,
    float* __restrict__ out, int write_hlast)
{
    #define CK 8
    #define NC (TT / CK)               // 64 chunks
    __shared__ ull xb[4][2][CK * 32];     // [pair][par][tc*32 + k] = {xp_b0, xp_b1}
    __shared__ ull pbuf[4][2][32 * (CK + 1)]; // [pair][par][k*9 + tc] = wo_k * h2
    __shared__ ull hbuf[4][2][HH];            // [pair][phase][k]

    const int wid  = threadIdx.x >> 5;
    const int lane = threadIdx.x & 31;
    const int pair = wid & 3;
    const int b0 = blockIdx.x * 8 + pair * 2;
    const ull z = pk(0.0f, 0.0f);

    if (wid < 4) {
        // ---------------- producer warp (one per SMSP) ----------------
        const int k = lane;
        ull wp2[HH];
        #pragma unroll
        for (int j = 0; j < HH; j++) { float w = W_hh[k * HH + j]; wp2[j] = pk(w, w); }
        const float wo = W_out[k];
        const ull wop = pk(wo, wo);

        float hA = h0[b0 * HH + k];
        float hB = h0[(b0 + 1) * HH + k];
        hbuf[pair][0][k] = pk(hA, hB);

        for (int c = 0; c < NC; c++) {
            pair_bar(pair);                    // xb[pair][c&1] ready, pbuf[c&1] free
            const ull* xq = xb[pair][c & 1];
            ull* pq = pbuf[pair][c & 1];
            #pragma unroll
            for (int tc = 0; tc < CK; tc++) {
                const int ph = tc & 1;
                ull a0 = xq[tc * 32 + k];      // LDS.64 (independent of h chain)
                ull a1 = z, a2 = z, a3 = z, a4 = z, a5 = z, a6 = z, a7 = z;
                const ulonglong2* hb2 = (const ulonglong2*)hbuf[pair][ph];
                #pragma unroll
                for (int m = 0; m < 16; m += 4) {
                    ulonglong2 h0v = hb2[m];
                    a0 = fma2(wp2[2 * m    ], h0v.x, a0);
                    a1 = fma2(wp2[2 * m + 1], h0v.y, a1);
                    ulonglong2 h1v = hb2[m + 1];
                    a2 = fma2(wp2[2 * m + 2], h1v.x, a2);
                    a3 = fma2(wp2[2 * m + 3], h1v.y, a3);
                    ulonglong2 h2v = hb2[m + 2];
                    a4 = fma2(wp2[2 * m + 4], h2v.x, a4);
                    a5 = fma2(wp2[2 * m + 5], h2v.y, a5);
                    ulonglong2 h3v = hb2[m + 3];
                    a6 = fma2(wp2[2 * m + 6], h3v.x, a6);
                    a7 = fma2(wp2[2 * m + 7], h3v.y, a7);
                }
                ull t0 = add2(a0, a4), t1 = add2(a1, a5);
                ull t2 = add2(a2, a6), t3 = add2(a3, a7);
                ull s = add2(add2(t0, t2), add2(t1, t3));
                float2 f = upk(s);
                hA = ftanh(f.x); hB = ftanh(f.y);
                ull h2 = pk(hA, hB);
                hbuf[pair][ph ^ 1][k] = h2;
                __syncwarp();
                pq[k * (CK + 1) + tc] = mul2(wop, h2);   // off-chain
            }
        }
        pair_bar(pair);                        // final pbuf chunk visible
        if (write_hlast) {
            float* hl = out + (size_t)BB * TT;
            hl[b0 * HH + k] = hA;
            hl[(b0 + 1) * HH + k] = hB;
        }
    } else {
        // ---------------- consumer warp ----------------
        const int l = lane;
        const float bo = b_out[0];
        const float4* src0 = (const float4*)(g_xp + (size_t)b0 * TT * HH);
        const float4* src1 = src0 + (TT * HH) / 4;

        // chunk loader: 2 KB -> xb[pair][par], packed f32x2 {b0,b1}
        auto loadx = [&](int c) {
            const float4* s0 = src0 + c * (CK * HH / 4);
            const float4* s1 = src1 + c * (CK * HH / 4);
            ulonglong2* dst = (ulonglong2*)xb[pair][c & 1];
            #pragma unroll
            for (int u = 0; u < 2; u++) {
                int e = u * 32 + l;            // float4 index 0..63
                float4 a = s0[e];
                float4 b = s1[e];
                int tc = e >> 3, kq = e & 7;
                dst[tc * 16 + kq * 2    ] = make_ulonglong2(pk(a.x, b.x), pk(a.y, b.y));
                dst[tc * 16 + kq * 2 + 1] = make_ulonglong2(pk(a.z, b.z), pk(a.w, b.w));
            }
        };
        // reduce chunk c: lane = tc + 8*kg; kg sums 8 k values, then shfl tree
        auto reduce = [&](int c) {
            const ull* pq = pbuf[pair][c & 1];
            const int tc = l & 7, kg = l >> 3;
            ull a0 = z, a1 = z;
            #pragma unroll
            for (int j = 0; j < 8; j += 2) {
                a0 = add2(a0, pq[(kg * 8 + j    ) * (CK + 1) + tc]);
                a1 = add2(a1, pq[(kg * 8 + j + 1) * (CK + 1) + tc]);
            }
            ull a = add2(a0, a1);
            a = add2(a, __shfl_xor_sync(0xffffffffu, a, 8));
            a = add2(a, __shfl_xor_sync(0xffffffffu, a, 16));
            if (kg == 0) {
                float2 f = upk(a);
                out[(size_t)b0 * TT + c * CK + tc]       = f.x + bo;
                out[(size_t)(b0 + 1) * TT + c * CK + tc] = f.y + bo;
            }
        };

        loadx(0);
        for (int c = 0; c < NC; c++) {
            pair_bar(pair);                    // publish xb[c&1]
            if (c + 1 < NC) loadx(c + 1);
            if (c > 0) reduce(c - 1);
        }
        pair_bar(pair);
        reduce(NC - 1);
    }
    #undef CK
    #undef NC
}

extern "C" void kernel_launch(void* const* d_in, const int* in_sizes, int n_in,
                              void* d_out, int out_size) {
    const float* x     = (const float*)d_in[0];
    const float* h0    = (const float*)d_in[1];
    const float* W_ih  = (const float*)d_in[2];
    const float* b_ih  = (const float*)d_in[3];
    const float* W_hh  = (const float*)d_in[4];
    const float* b_hh  = (const float*)d_in[5];
    const float* W_out = (const float*)d_in[6];
    const float* b_out = (const float*)d_in[7];
    float* out = (float*)d_out;

    xproj_kernel<<<(BB * TT) / 256, 128>>>(x, W_ih, b_ih, b_hh);

    int wh = (out_size >= BB * TT + BB * HH) ? 1 : 0;
    rnn_kernel<<<BB / 8, 256>>>(h0, W_hh, W_out, b_out, out, wh);
}